// round 11
// baseline (speedup 1.0000x reference)
#include <cuda_runtime.h>

#define DT 0.05f
#define NSTEPS 41
#define MAXBLK 8192

typedef unsigned long long u64;

// Per-block partial sums — written (not accumulated) by every block each run,
// so no zeroing pass is needed. [0..MAXBLK): cost, [MAXBLK..2*MAXBLK): nor.
__device__ float g_partial[2 * MAXBLK];

// Single-instruction HW tanh (MUFU.TANH). Max abs err ~2^-11; measured
// end-to-end rel_err 2.2e-7 on this workload.
__device__ __forceinline__ float ftanh(float x) {
    float y;
    asm("tanh.approx.f32 %0, %1;" : "=f"(y) : "f"(x));
    return y;
}

// ---- packed f32x2 helpers (sm_10x FFMA2/FMUL2 path; ALU-pipe pack/unpack) ----
__device__ __forceinline__ u64 pack2(float lo, float hi) {
    u64 r; asm("mov.b64 %0, {%1, %2};" : "=l"(r) : "f"(lo), "f"(hi)); return r;
}
__device__ __forceinline__ void unpack2(u64 v, float& lo, float& hi) {
    asm("mov.b64 {%0, %1}, %2;" : "=f"(lo), "=f"(hi) : "l"(v));
}
__device__ __forceinline__ u64 fma2(u64 a, u64 b, u64 c) {
    u64 r; asm("fma.rn.f32x2 %0, %1, %2, %3;" : "=l"(r) : "l"(a), "l"(b), "l"(c)); return r;
}
__device__ __forceinline__ u64 mul2(u64 a, u64 b) {
    u64 r; asm("mul.rn.f32x2 %0, %1, %2;" : "=l"(r) : "l"(a), "l"(b)); return r;
}

__global__ void __launch_bounds__(256)
sim_kernel(const float* __restrict__ omega,
           const float* __restrict__ Wh1, const float* __restrict__ bh1,
           const float* __restrict__ Wh2, const float* __restrict__ bh2,
           const float* __restrict__ Wr1, const float* __restrict__ br1,
           const float* __restrict__ Wr2, const float* __restrict__ br2,
           int N)
{
    const int i = blockIdx.x * blockDim.x + threadIdx.x;

    // Tiny shared weights -> registers (uniform broadcast loads).
    float wh1[16], vbh1[4], wh2[4], wr1[9], vbr1[3], wr2[3];
#pragma unroll
    for (int k = 0; k < 16; k++) wh1[k] = Wh1[k];
#pragma unroll
    for (int k = 0; k < 4; k++)  vbh1[k] = bh1[k];
#pragma unroll
    for (int k = 0; k < 4; k++)  wh2[k] = Wh2[k];
    const float vbh2 = bh2[0];
#pragma unroll
    for (int k = 0; k < 9; k++)  wr1[k] = Wr1[k];
#pragma unroll
    for (int k = 0; k < 3; k++)  vbr1[k] = br1[k];
#pragma unroll
    for (int k = 0; k < 3; k++)  wr2[k] = Wr2[k];
    const float vbr2 = br2[0];

    float cost = 0.0f, nor = 0.0f;

    if (i < N) {
        const float t0 = omega[i];       // s_star[0]
        const float t1 = omega[N + i];   // s_star[1]

        // Loop-invariant hoist: first-layer target contributions + bias.
        const float ph0 = wh1[0]  * t0 + wh1[1]  * t1 + vbh1[0];
        const float ph1 = wh1[4]  * t0 + wh1[5]  * t1 + vbh1[1];
        const float ph2 = wh1[8]  * t0 + wh1[9]  * t1 + vbh1[2];
        const float ph3 = wh1[12] * t0 + wh1[13] * t1 + vbh1[3];

        // Packed loop-invariant constants.
        const u64 t01     = pack2(t0, t1);
        const u64 negone2 = pack2(-1.0f, -1.0f);
        const u64 qcoef2  = pack2(10.0f, 1.0f);   // err weights diag(10,1)
        const u64 dt2     = pack2(DT, DT);
        const u64 ph01    = pack2(ph0, ph1);
        const u64 ph23    = pack2(ph2, ph3);
        const u64 cA01    = pack2(wh1[2],  wh1[6]);   // s0 coefs, neurons 0,1
        const u64 cB01    = pack2(wh1[3],  wh1[7]);   // s1 coefs, neurons 0,1
        const u64 cA23    = pack2(wh1[10], wh1[14]);  // s0 coefs, neurons 2,3
        const u64 cB23    = pack2(wh1[11], wh1[15]);  // s1 coefs, neurons 2,3
        const u64 rb01    = pack2(vbr1[0], vbr1[1]);
        const u64 cR0     = pack2(wr1[0], wr1[3]);    // s0 coefs, robot 0,1
        const u64 cR1     = pack2(wr1[1], wr1[4]);    // s1 coefs, robot 0,1
        const u64 cR2     = pack2(wr1[2], wr1[5]);    // z  coefs, robot 0,1

        u64 s01  = pack2(0.0f, 0.0f);   // state (s0, s1)
        u64 errp = pack2(0.0f, 0.0f);   // packed err accumulator (10*e0^2 | e1^2)
        float eff = 0.0f;

#pragma unroll 1
        for (int t = 0; t < NSTEPS - 1; t++) {
            float s0, s1;
            unpack2(s01, s0, s1);
            const u64 s00 = pack2(s0, s0);
            const u64 s11 = pack2(s1, s1);

            // e = s_star - s (packed), err += (10,1) . e*e
            const u64 e01 = fma2(s01, negone2, t01);
            const u64 q   = mul2(e01, e01);
            errp = fma2(q, qcoef2, errp);

            float e0, e1;
            unpack2(e01, e0, e1);
            const float zt = fmaf(0.1f, e1, e0);

            // human MLP first layer: two packed neuron pairs
            u64 hA = fma2(s00, cA01, ph01);
            hA = fma2(s11, cB01, hA);
            u64 hB = fma2(s00, cA23, ph23);
            hB = fma2(s11, cB23, hB);
            float x0, x1, x2, x3;
            unpack2(hA, x0, x1);
            unpack2(hB, x2, x3);
            const float h0 = ftanh(x0), h1 = ftanh(x1);
            const float h2 = ftanh(x2), h3 = ftanh(x3);
            const float z = ftanh(h0 * wh2[0] + h1 * wh2[1] + h2 * wh2[2] + h3 * wh2[3] + vbh2);

            // robot MLP: neurons (0,1) packed, neuron 2 scalar
            const u64 zz = pack2(z, z);
            u64 rA = fma2(s00, cR0, rb01);
            rA = fma2(s11, cR1, rA);
            rA = fma2(zz,  cR2, rA);
            float y0, y1;
            unpack2(rA, y0, y1);
            const float r0 = ftanh(y0);
            const float r1 = ftanh(y1);
            const float r2 = ftanh(wr1[6] * s0 + wr1[7] * s1 + wr1[8] * z + vbr1[2]);
            const float a = r0 * wr2[0] + r1 * wr2[1] + r2 * wr2[2] + vbr2;

            // s_next = (s0 + dt*s1, s1 + dt*a)  — one packed FFMA2
            s01 = fma2(pack2(s1, a), dt2, s01);

            eff += (fabsf(z) > 0.01f) ? 1.0f : 0.0f;
            const float d = zt - z;
            nor = fmaf(d, d, nor);
        }
        // final error term
        const u64 e01 = fma2(s01, negone2, t01);
        const u64 q   = mul2(e01, e01);
        errp = fma2(q, qcoef2, errp);

        float errlo, errhi;
        unpack2(errp, errlo, errhi);
        cost = errlo + errhi + eff;
    }

    // ---- block reduction: warp shuffle -> shared -> per-block partial store
#pragma unroll
    for (int off = 16; off > 0; off >>= 1) {
        cost += __shfl_down_sync(0xffffffffu, cost, off);
        nor  += __shfl_down_sync(0xffffffffu, nor,  off);
    }
    __shared__ float sc[8], sn[8];
    const int lane = threadIdx.x & 31;
    const int w    = threadIdx.x >> 5;
    if (lane == 0) { sc[w] = cost; sn[w] = nor; }
    __syncthreads();
    if (threadIdx.x == 0) {
        float c = 0.0f, n = 0.0f;
#pragma unroll
        for (int k = 0; k < 8; k++) { c += sc[k]; n += sn[k]; }
        g_partial[blockIdx.x]           = c;   // plain store: no zeroing pass
        g_partial[MAXBLK + blockIdx.x]  = n;
    }
}

__global__ void __launch_bounds__(256)
finalize_kernel(const float* __restrict__ alpha,
                float* __restrict__ out, int N, int nblocks)
{
    // Reduce per-block partials in double.
    double c = 0.0, n = 0.0;
    for (int k = threadIdx.x; k < nblocks; k += 256) {
        c += (double)g_partial[k];
        n += (double)g_partial[MAXBLK + k];
    }
    __shared__ double dc[256], dn[256];
    dc[threadIdx.x] = c; dn[threadIdx.x] = n;
    __syncthreads();
    for (int s = 128; s > 0; s >>= 1) {
        if (threadIdx.x < s) {
            dc[threadIdx.x] += dc[threadIdx.x + s];
            dn[threadIdx.x] += dn[threadIdx.x + s];
        }
        __syncthreads();
    }
    if (threadIdx.x == 0) {
        const double inv = 1.0 / (double)N;
        out[0] = (float)(dc[0] * inv + (double)alpha[0] * (dn[0] * inv));
    }
}

extern "C" void kernel_launch(void* const* d_in, const int* in_sizes, int n_in,
                              void* d_out, int out_size)
{
    const float* omega = (const float*)d_in[0];
    const float* Wh1   = (const float*)d_in[1];
    const float* bh1   = (const float*)d_in[2];
    const float* Wh2   = (const float*)d_in[3];
    const float* bh2   = (const float*)d_in[4];
    const float* Wr1   = (const float*)d_in[5];
    const float* br1   = (const float*)d_in[6];
    const float* Wr2   = (const float*)d_in[7];
    const float* br2   = (const float*)d_in[8];
    const float* alpha = (const float*)d_in[9];

    const int N = in_sizes[0] / 2;   // omega is [2, N]

    const int threads = 256;
    int blocks = (N + threads - 1) / threads;
    if (blocks > MAXBLK) blocks = MAXBLK;  // N=1M -> 4096, safety clamp
    sim_kernel<<<blocks, threads>>>(omega, Wh1, bh1, Wh2, bh2,
                                    Wr1, br1, Wr2, br2, N);
    finalize_kernel<<<1, 256>>>(alpha, (float*)d_out, N, blocks);
}

// round 13
// speedup vs baseline: 1.0764x; 1.0764x over previous
#include <cuda_runtime.h>

#define DT 0.05f
#define NSTEPS 41

typedef unsigned long long u64;

// Accumulators — zero-initialized at load; finalize_kernel re-zeroes them
// after each read, so every launch (and every graph replay) starts from 0.
__device__ double g_acc[2];

// Single-instruction HW tanh (MUFU.TANH). Max abs err ~2^-11; measured
// end-to-end rel_err 2.2e-7 on this workload.
__device__ __forceinline__ float ftanh(float x) {
    float y;
    asm("tanh.approx.f32 %0, %1;" : "=f"(y) : "f"(x));
    return y;
}

// ---- packed f32x2 helpers (sm_10x FFMA2/FMUL2 path; ALU-pipe pack/unpack) ----
__device__ __forceinline__ u64 pack2(float lo, float hi) {
    u64 r; asm("mov.b64 %0, {%1, %2};" : "=l"(r) : "f"(lo), "f"(hi)); return r;
}
__device__ __forceinline__ void unpack2(u64 v, float& lo, float& hi) {
    asm("mov.b64 {%0, %1}, %2;" : "=f"(lo), "=f"(hi) : "l"(v));
}
__device__ __forceinline__ u64 fma2(u64 a, u64 b, u64 c) {
    u64 r; asm("fma.rn.f32x2 %0, %1, %2, %3;" : "=l"(r) : "l"(a), "l"(b), "l"(c)); return r;
}
__device__ __forceinline__ u64 mul2(u64 a, u64 b) {
    u64 r; asm("mul.rn.f32x2 %0, %1, %2;" : "=l"(r) : "l"(a), "l"(b)); return r;
}

__global__ void __launch_bounds__(256)
sim_kernel(const float* __restrict__ omega,
           const float* __restrict__ Wh1, const float* __restrict__ bh1,
           const float* __restrict__ Wh2, const float* __restrict__ bh2,
           const float* __restrict__ Wr1, const float* __restrict__ br1,
           const float* __restrict__ Wr2, const float* __restrict__ br2,
           int N)
{
    const int i = blockIdx.x * blockDim.x + threadIdx.x;

    // Tiny shared weights -> registers (uniform broadcast loads).
    float wh1[16], vbh1[4], wh2[4], wr1[9], vbr1[3], wr2[3];
#pragma unroll
    for (int k = 0; k < 16; k++) wh1[k] = Wh1[k];
#pragma unroll
    for (int k = 0; k < 4; k++)  vbh1[k] = bh1[k];
#pragma unroll
    for (int k = 0; k < 4; k++)  wh2[k] = Wh2[k];
    const float vbh2 = bh2[0];
#pragma unroll
    for (int k = 0; k < 9; k++)  wr1[k] = Wr1[k];
#pragma unroll
    for (int k = 0; k < 3; k++)  vbr1[k] = br1[k];
#pragma unroll
    for (int k = 0; k < 3; k++)  wr2[k] = Wr2[k];
    const float vbr2 = br2[0];

    float cost = 0.0f, nor = 0.0f;

    if (i < N) {
        const float t0 = omega[i];       // s_star[0]
        const float t1 = omega[N + i];   // s_star[1]

        // Loop-invariant hoist: first-layer target contributions + bias.
        const float ph0 = wh1[0]  * t0 + wh1[1]  * t1 + vbh1[0];
        const float ph1 = wh1[4]  * t0 + wh1[5]  * t1 + vbh1[1];
        const float ph2 = wh1[8]  * t0 + wh1[9]  * t1 + vbh1[2];
        const float ph3 = wh1[12] * t0 + wh1[13] * t1 + vbh1[3];

        // Packed loop-invariant constants.
        const u64 t01     = pack2(t0, t1);
        const u64 negone2 = pack2(-1.0f, -1.0f);
        const u64 qcoef2  = pack2(10.0f, 1.0f);   // err weights diag(10,1)
        const u64 dt2     = pack2(DT, DT);
        const u64 ph01    = pack2(ph0, ph1);
        const u64 ph23    = pack2(ph2, ph3);
        const u64 cA01    = pack2(wh1[2],  wh1[6]);   // s0 coefs, neurons 0,1
        const u64 cB01    = pack2(wh1[3],  wh1[7]);   // s1 coefs, neurons 0,1
        const u64 cA23    = pack2(wh1[10], wh1[14]);  // s0 coefs, neurons 2,3
        const u64 cB23    = pack2(wh1[11], wh1[15]);  // s1 coefs, neurons 2,3
        const u64 rb01    = pack2(vbr1[0], vbr1[1]);
        const u64 cR0     = pack2(wr1[0], wr1[3]);    // s0 coefs, robot 0,1
        const u64 cR1     = pack2(wr1[1], wr1[4]);    // s1 coefs, robot 0,1
        const u64 cR2     = pack2(wr1[2], wr1[5]);    // z  coefs, robot 0,1

        u64 s01  = pack2(0.0f, 0.0f);   // state (s0, s1)
        u64 errp = pack2(0.0f, 0.0f);   // packed err accumulator (10*e0^2 | e1^2)
        float eff = 0.0f;

#pragma unroll 1
        for (int t = 0; t < NSTEPS - 1; t++) {
            float s0, s1;
            unpack2(s01, s0, s1);
            const u64 s00 = pack2(s0, s0);
            const u64 s11 = pack2(s1, s1);

            // e = s_star - s (packed), err += (10,1) . e*e
            const u64 e01 = fma2(s01, negone2, t01);
            const u64 q   = mul2(e01, e01);
            errp = fma2(q, qcoef2, errp);

            float e0, e1;
            unpack2(e01, e0, e1);
            const float zt = fmaf(0.1f, e1, e0);

            // human MLP first layer: two packed neuron pairs
            u64 hA = fma2(s00, cA01, ph01);
            hA = fma2(s11, cB01, hA);
            u64 hB = fma2(s00, cA23, ph23);
            hB = fma2(s11, cB23, hB);
            float x0, x1, x2, x3;
            unpack2(hA, x0, x1);
            unpack2(hB, x2, x3);
            const float h0 = ftanh(x0), h1 = ftanh(x1);
            const float h2 = ftanh(x2), h3 = ftanh(x3);
            const float z = ftanh(h0 * wh2[0] + h1 * wh2[1] + h2 * wh2[2] + h3 * wh2[3] + vbh2);

            // robot MLP: neurons (0,1) packed, neuron 2 scalar
            const u64 zz = pack2(z, z);
            u64 rA = fma2(s00, cR0, rb01);
            rA = fma2(s11, cR1, rA);
            rA = fma2(zz,  cR2, rA);
            float y0, y1;
            unpack2(rA, y0, y1);
            const float r0 = ftanh(y0);
            const float r1 = ftanh(y1);
            const float r2 = ftanh(wr1[6] * s0 + wr1[7] * s1 + wr1[8] * z + vbr1[2]);
            const float a = r0 * wr2[0] + r1 * wr2[1] + r2 * wr2[2] + vbr2;

            // s_next = (s0 + dt*s1, s1 + dt*a)  — one packed FFMA2
            s01 = fma2(pack2(s1, a), dt2, s01);

            eff += (fabsf(z) > 0.01f) ? 1.0f : 0.0f;
            const float d = zt - z;
            nor = fmaf(d, d, nor);
        }
        // final error term
        const u64 e01 = fma2(s01, negone2, t01);
        const u64 q   = mul2(e01, e01);
        errp = fma2(q, qcoef2, errp);

        float errlo, errhi;
        unpack2(errp, errlo, errhi);
        cost = errlo + errhi + eff;
    }

    // ---- block reduction: warp shuffle -> shared -> one double atomic/block
#pragma unroll
    for (int off = 16; off > 0; off >>= 1) {
        cost += __shfl_down_sync(0xffffffffu, cost, off);
        nor  += __shfl_down_sync(0xffffffffu, nor,  off);
    }
    __shared__ float sc[8], sn[8];
    const int lane = threadIdx.x & 31;
    const int w    = threadIdx.x >> 5;
    if (lane == 0) { sc[w] = cost; sn[w] = nor; }
    __syncthreads();
    if (threadIdx.x == 0) {
        float c = 0.0f, n = 0.0f;
#pragma unroll
        for (int k = 0; k < 8; k++) { c += sc[k]; n += sn[k]; }
        atomicAdd(&g_acc[0], (double)c);
        atomicAdd(&g_acc[1], (double)n);
    }
}

__global__ void finalize_kernel(const float* __restrict__ alpha,
                                float* __restrict__ out, int N)
{
    const double inv = 1.0 / (double)N;
    out[0] = (float)(g_acc[0] * inv + (double)alpha[0] * (g_acc[1] * inv));
    // Reset for the next launch/replay — keeps every call starting from 0.
    g_acc[0] = 0.0;
    g_acc[1] = 0.0;
}

extern "C" void kernel_launch(void* const* d_in, const int* in_sizes, int n_in,
                              void* d_out, int out_size)
{
    const float* omega = (const float*)d_in[0];
    const float* Wh1   = (const float*)d_in[1];
    const float* bh1   = (const float*)d_in[2];
    const float* Wh2   = (const float*)d_in[3];
    const float* bh2   = (const float*)d_in[4];
    const float* Wr1   = (const float*)d_in[5];
    const float* br1   = (const float*)d_in[6];
    const float* Wr2   = (const float*)d_in[7];
    const float* br2   = (const float*)d_in[8];
    const float* alpha = (const float*)d_in[9];

    const int N = in_sizes[0] / 2;   // omega is [2, N]

    const int threads = 256;
    const int blocks  = (N + threads - 1) / threads;
    sim_kernel<<<blocks, threads>>>(omega, Wh1, bh1, Wh2, bh2,
                                    Wr1, br1, Wr2, br2, N);
    finalize_kernel<<<1, 1>>>(alpha, (float*)d_out, N);
}